// round 10
// baseline (speedup 1.0000x reference)
#include <cuda_runtime.h>

// upfirdn2d(up=2, down=1, pad=5), 12x12 separable K = h h^T, via fma.rn.f32x2.
// Proven skeleton: parity-pair outputs, broadcast-input FFMA2, sliding register
// windows, simple idx-based load loop (high MLP).
// R9: 128x128 output tile, 512 threads, dynamic smem (~54KB) -> halo 1.163,
// 4 blocks/SM x 512 thr; immediate-offset output stores.

#define IMG_H 256
#define IMG_W 256
#define OUT_H 511
#define OUT_W 511
#define TILE_W 128
#define TILE_H 128
#define IN_W  69      // input cols per 128-wide output tile
#define IN_H  69      // input rows per 128-tall output tile
#define SPITCH 69     // stride mod 32 = 5 -> conflict-free s_in column reads
#define TP2   65      // float2 pitch for tmp rows (130 floats)
#define NTHR  512

__device__ __forceinline__ float2 ffma2(float2 a, float2 b, float2 c) {
    float2 d;
    asm("fma.rn.f32x2 %0, %1, %2, %3;"
        : "=l"(*reinterpret_cast<unsigned long long*>(&d))
        : "l"(*reinterpret_cast<unsigned long long*>(&a)),
          "l"(*reinterpret_cast<unsigned long long*>(&b)),
          "l"(*reinterpret_cast<unsigned long long*>(&c)));
    return d;
}

__device__ __forceinline__ float2 fmul2(float2 a, float2 b) {
    float2 d;
    asm("mul.rn.f32x2 %0, %1, %2;"
        : "=l"(*reinterpret_cast<unsigned long long*>(&d))
        : "l"(*reinterpret_cast<unsigned long long*>(&a)),
          "l"(*reinterpret_cast<unsigned long long*>(&b)));
    return d;
}

__device__ __forceinline__ float2 bcast(float w) { return make_float2(w, w); }

// dynamic smem layout (bytes)
#define SM_IN_OFF   0
#define SM_IN_BYTES (IN_H * SPITCH * 4)                 // 19044
#define SM_TMP_OFF  ((SM_IN_OFF + SM_IN_BYTES + 15) & ~15)
#define SM_TMP_BYTES (IN_H * TP2 * 8)                   // 35880
#define SM_TOTAL    (SM_TMP_OFF + SM_TMP_BYTES)

__global__ __launch_bounds__(NTHR)
void lpf_up2_kernel(const float* __restrict__ x,
                    const float* __restrict__ K,
                    float* __restrict__ out) {
    extern __shared__ char smem[];
    float*  s_in  = reinterpret_cast<float*>(smem + SM_IN_OFF);
    float2* s_tmp = reinterpret_cast<float2*>(smem + SM_TMP_OFF);
    __shared__ float2 s_c[6];                // (h_even_tap[t], h_odd_tap[t])

    const int tid = threadIdx.x;
    const int img = blockIdx.z;
    const int ox0 = blockIdx.x * TILE_W;     // even
    const int oy0 = blockIdx.y * TILE_H;     // even
    const int mx0 = (ox0 >> 1) - 2;
    const int my0 = (oy0 >> 1) - 2;

    // Recover separable h from K row 5: h[j] = K[5][j] / sqrt(K[5][5]).
    // Sign ambiguity cancels (all taps are h*h products).
    if (tid < 6) {
        float s = rsqrtf(K[5 * 12 + 5]);
        s_c[tid] = make_float2(K[5 * 12 + (10 - 2 * tid)] * s,
                               K[5 * 12 + (11 - 2 * tid)] * s);
    }

    // ---- Load input tile (independent iterations -> high MLP) ----
    const float* __restrict__ xin = x + (size_t)img * (IMG_H * IMG_W);
    #pragma unroll
    for (int it = 0; it < 10; it++) {
        int idx = tid + NTHR * it;
        if (idx < IN_H * IN_W) {
            int r = idx / IN_W;
            int c = idx - r * IN_W;
            int gy = my0 + r;
            int gx = mx0 + c;
            float v = 0.0f;
            if ((unsigned)gy < IMG_H && (unsigned)gx < IMG_W)
                v = xin[gy * IMG_W + gx];
            s_in[r * SPITCH + c] = v;
        }
    }
    __syncthreads();

    const float2 c0 = s_c[0], c1 = s_c[1], c2 = s_c[2],
                 c3 = s_c[3], c4 = s_c[4], c5 = s_c[5];

    // ---- Horizontal pass: tmp[r][pair k] = sum_t c[t]*s_in[r][k+t] ----
    // 69 rows x 8 groups of 8 pairs = 552 tasks; threads 0..39 take 2nd slot.
    #pragma unroll
    for (int tt = 0; tt < 2; tt++) {
        int t = tid + NTHR * tt;
        if (t < IN_H * 8) {
            int kg = t / IN_H;            // 0..7
            int r  = t - kg * IN_H;       // 0..68
            int k0 = kg * 8;
            const float* row = s_in + r * SPITCH + k0;
            float2* trow = s_tmp + r * TP2 + k0;
            float2 p0 = bcast(row[0]), p1 = bcast(row[1]),
                   p2 = bcast(row[2]), p3 = bcast(row[3]),
                   p4 = bcast(row[4]), p5 = bcast(row[5]);
            #pragma unroll
            for (int j = 0; j < 8; j++) {
                float2 acc = fmul2(p0, c0);
                acc = ffma2(p1, c1, acc);
                acc = ffma2(p2, c2, acc);
                acc = ffma2(p3, c3, acc);
                acc = ffma2(p4, c4, acc);
                acc = ffma2(p5, c5, acc);
                trow[j] = acc;
                p0 = p1; p1 = p2; p2 = p3; p3 = p4; p4 = p5;
                if (j < 7) p5 = bcast(row[j + 6]);   // max col offset 68
            }
        }
    }
    __syncthreads();

    // ---- Vertical pass: out rows (2J, 2J+1) = sum_t c[t]*tmp[J+t][ox] ----
    // 128 columns x 4 groups of 16 row-pairs = 512 threads exactly.
    const int ox = tid & 127;
    const int j0 = (tid >> 7) * 16;     // 0,16,32,48
    const float* tcol = reinterpret_cast<const float*>(s_tmp) + j0 * (TP2 * 2) + ox;
    float2 v0 = bcast(tcol[0 * (TP2 * 2)]);
    float2 v1 = bcast(tcol[1 * (TP2 * 2)]);
    float2 v2 = bcast(tcol[2 * (TP2 * 2)]);
    float2 v3 = bcast(tcol[3 * (TP2 * 2)]);
    float2 v4 = bcast(tcol[4 * (TP2 * 2)]);
    float2 v5 = bcast(tcol[5 * (TP2 * 2)]);

    const int  gox = ox0 + ox;
    const bool xok = (gox < OUT_W);
    // Base pointer; per-j store offsets are compile-time immediates.
    float* __restrict__ p =
        out + (size_t)img * ((size_t)OUT_H * OUT_W) +
        (size_t)(oy0 + 2 * j0) * OUT_W + gox;
    // Only block row oy0=384, group j0=48, j=15 would write row 511: skip it.
    const bool lastgrp = (oy0 + 2 * j0 == 480);

    #pragma unroll
    for (int j = 0; j < 16; j++) {
        float2 acc = fmul2(v0, c0);
        acc = ffma2(v1, c1, acc);
        acc = ffma2(v2, c2, acc);
        acc = ffma2(v3, c3, acc);
        acc = ffma2(v4, c4, acc);
        acc = ffma2(v5, c5, acc);
        if (xok) {
            p[(size_t)(2 * j) * OUT_W] = acc.x;            // even row <= 510
            if (!lastgrp || j < 15)                         // skip row 511
                p[(size_t)(2 * j + 1) * OUT_W] = acc.y;
        }
        v0 = v1; v1 = v2; v2 = v3; v3 = v4; v4 = v5;
        if (j < 15) v5 = bcast(tcol[(j + 6) * (TP2 * 2)]); // max row j0+20 <= 68
    }
}

extern "C" void kernel_launch(void* const* d_in, const int* in_sizes, int n_in,
                              void* d_out, int out_size) {
    const float* x = (const float*)d_in[0];   // [8,64,256,256] f32
    const float* K = (const float*)d_in[1];   // [12,12] f32
    float* out = (float*)d_out;               // [8,64,511,511] f32

    static bool attr_done = false;            // attribute set is idempotent
    if (!attr_done) {
        cudaFuncSetAttribute(lpf_up2_kernel,
                             cudaFuncAttributeMaxDynamicSharedMemorySize,
                             SM_TOTAL);
        attr_done = true;
    }

    int imgs = in_sizes[0] / (IMG_H * IMG_W); // 512
    dim3 grid((OUT_W + TILE_W - 1) / TILE_W,  // 4
              (OUT_H + TILE_H - 1) / TILE_H,  // 4
              imgs);                          // 512
    lpf_up2_kernel<<<grid, NTHR, SM_TOTAL>>>(x, K, out);
}